// round 1
// baseline (speedup 1.0000x reference)
#include <cuda_runtime.h>
#include <math.h>

#define Bn 64
#define Tn 512
#define Cn 384
#define Hn 6
#define HDn 64
#define FFn 1536
#define BTn (Bn*Tn)
#define EPSn 1e-5f

// ---------------- scratch (device globals; no runtime allocation) ----------------
__device__ float g_wq[Cn*Cn];
__device__ float g_wk[Cn*Cn];
__device__ float g_wv[Cn*Cn];
__device__ float g_q[(size_t)Bn*Hn*Tn*HDn];
__device__ float g_k[(size_t)Bn*Hn*Tn*HDn];
__device__ float g_v[(size_t)Bn*Hn*Tn*HDn];
__device__ float g_o[(size_t)BTn*Cn];
__device__ float g_p[(size_t)BTn*Cn];
__device__ float g_r1[(size_t)BTn*Cn];
__device__ float g_r2[(size_t)BTn*Cn];
__device__ float g_h[(size_t)BTn*FFn];

// ---------------- weight repack: [H, C, HD] -> [C, H*HD] row-major ----------------
__global__ void repack_w(const float* __restrict__ w, float* __restrict__ o, int n) {
    int i = blockIdx.x * blockDim.x + threadIdx.x;
    if (i < n) {
        int d = i & (HDn - 1);
        int c = (i >> 6) % Cn;
        int h = i / (HDn * Cn);
        o[c * (Hn * HDn) + h * HDn + d] = w[i];
    }
}

// ---------------- SGEMM 128x128x8, 256 threads, 8x8 per-thread tiles ----------------
// flags: bit0 = relu, bit1 = scatter output to [B,H,T,HD] layout (requires T=512, HD=64)
__global__ __launch_bounds__(256) void sgemm128(
    const float* __restrict__ A, const float* __restrict__ Bm,
    const float* __restrict__ bias, float* __restrict__ Cout,
    int M, int N, int K, int flags)
{
    __shared__ float As[8][128];
    __shared__ float Bs[8][128];
    const int tid = threadIdx.x;
    const int bm = blockIdx.y * 128;
    const int bn = blockIdx.x * 128;
    const int tx = tid & 15, ty = tid >> 4;
    const int row0 = ty * 8, col0 = tx * 8;
    const int aRow = tid >> 1, aCol = (tid & 1) * 4;
    const int bRow = tid >> 5, bCol = (tid & 31) * 4;
    const float* Ap = A + (size_t)(bm + aRow) * K + aCol;
    const float* Bp = Bm + (size_t)bRow * N + bn + bCol;

    float acc[8][8];
#pragma unroll
    for (int i = 0; i < 8; i++)
#pragma unroll
        for (int j = 0; j < 8; j++) acc[i][j] = 0.f;

    for (int k0 = 0; k0 < K; k0 += 8) {
        float4 av = *(const float4*)(Ap + k0);
        As[aCol + 0][aRow] = av.x;
        As[aCol + 1][aRow] = av.y;
        As[aCol + 2][aRow] = av.z;
        As[aCol + 3][aRow] = av.w;
        *(float4*)(&Bs[bRow][bCol]) = *(const float4*)(Bp + (size_t)k0 * N);
        __syncthreads();
#pragma unroll
        for (int kk = 0; kk < 8; ++kk) {
            float a[8], b[8];
            *(float4*)(a)     = *(const float4*)(&As[kk][row0]);
            *(float4*)(a + 4) = *(const float4*)(&As[kk][row0 + 4]);
            *(float4*)(b)     = *(const float4*)(&Bs[kk][col0]);
            *(float4*)(b + 4) = *(const float4*)(&Bs[kk][col0 + 4]);
#pragma unroll
            for (int i = 0; i < 8; i++)
#pragma unroll
                for (int j = 0; j < 8; j++)
                    acc[i][j] = fmaf(a[i], b[j], acc[i][j]);
        }
        __syncthreads();
    }

    const bool relu = (flags & 1) != 0;
    const bool bhtd = (flags & 2) != 0;
#pragma unroll
    for (int i = 0; i < 8; i++) {
        int gr = bm + row0 + i;
#pragma unroll
        for (int j = 0; j < 8; j++) {
            int gc = bn + col0 + j;
            float v = acc[i][j] + bias[gc];
            if (relu) v = fmaxf(v, 0.f);
            if (bhtd) {
                int bb = gr >> 9;      // / T (512)
                int t  = gr & 511;
                int h  = gc >> 6;      // / HD (64)
                int d  = gc & 63;
                Cout[(((size_t)(bb * Hn + h)) * Tn + t) * HDn + d] = v;
            } else {
                Cout[(size_t)gr * N + gc] = v;
            }
        }
    }
}

// ---------------- RoPE (reference: angle = position t, same for all pairs) ----------------
__global__ void rope_k(float* __restrict__ a, int npairs) {
    int i = blockIdx.x * blockDim.x + threadIdx.x;
    if (i >= npairs) return;
    int row = i >> 5;          // [B*H*T]
    int t = row % Tn;
    float s, c;
    sincosf((float)t, &s, &c);
    float xr = a[2 * i];
    float xi = a[2 * i + 1];
    a[2 * i]     = c * xr - s * xi;
    a[2 * i + 1] = s * xr + c * xi;
}

// ---------------- causal flash attention: 8 warps/block = 8 queries ----------------
__global__ __launch_bounds__(256) void attn_k(
    const float* __restrict__ q, const float* __restrict__ k,
    const float* __restrict__ v, float* __restrict__ o)
{
    const int bh = blockIdx.y;              // b*H + h
    const int warp = threadIdx.x >> 5, lane = threadIdx.x & 31;
    const int t = blockIdx.x * 8 + warp;
    const size_t base = (size_t)bh * Tn * HDn;
    __shared__ float Ks[32][64];
    __shared__ float Vs[32][64];

    const float q_a = q[base + (size_t)t * 64 + lane];
    const float q_b = q[base + (size_t)t * 64 + 32 + lane];

    float m = -INFINITY, l = 0.f, acc_a = 0.f, acc_b = 0.f;
    const int tmax = blockIdx.x * 8 + 7;
    const float scale = 0.051031036307982884f;  // 1/sqrt(C) = 1/sqrt(384)

    for (int s0 = 0; s0 <= tmax; s0 += 32) {
        __syncthreads();
        for (int i = threadIdx.x; i < 32 * 64; i += 256) {
            int ss = i >> 6, d = i & 63;
            Ks[ss][d] = k[base + (size_t)(s0 + ss) * 64 + d];
            Vs[ss][d] = v[base + (size_t)(s0 + ss) * 64 + d];
        }
        __syncthreads();
        int jmax = min(32, tmax - s0 + 1);
        for (int j = 0; j < jmax; ++j) {
            float p = q_a * Ks[j][lane] + q_b * Ks[j][lane + 32];
            p += __shfl_xor_sync(0xffffffffu, p, 16);
            p += __shfl_xor_sync(0xffffffffu, p, 8);
            p += __shfl_xor_sync(0xffffffffu, p, 4);
            p += __shfl_xor_sync(0xffffffffu, p, 2);
            p += __shfl_xor_sync(0xffffffffu, p, 1);
            int s = s0 + j;
            if (s <= t) {
                float sc = p * scale;
                float mn = fmaxf(m, sc);
                float corr = __expf(m - mn);
                float pe = __expf(sc - mn);
                l = l * corr + pe;
                acc_a = acc_a * corr + pe * Vs[j][lane];
                acc_b = acc_b * corr + pe * Vs[j][lane + 32];
                m = mn;
            }
        }
    }
    const int b = bh / Hn, h = bh % Hn;
    const float inv = 1.f / l;
    size_t ob = ((size_t)(b * Tn + t)) * Cn + h * HDn;
    o[ob + lane]      = acc_a * inv;
    o[ob + 32 + lane] = acc_b * inv;
}

// ---------------- fused residual-add + LayerNorm (row = 384) ----------------
__global__ __launch_bounds__(128) void ln_res_k(
    const float* __restrict__ x, const float* __restrict__ y,
    const float* __restrict__ g, const float* __restrict__ bb,
    float* __restrict__ out)
{
    __shared__ float red[4];
    const int row = blockIdx.x;
    const int tid = threadIdx.x;  // 128 threads, 3 elems each
    const size_t base = (size_t)row * Cn;
    float v0 = x[base + tid]       + y[base + tid];
    float v1 = x[base + tid + 128] + y[base + tid + 128];
    float v2 = x[base + tid + 256] + y[base + tid + 256];

    float s = v0 + v1 + v2;
    for (int o = 16; o > 0; o >>= 1) s += __shfl_xor_sync(0xffffffffu, s, o);
    if ((tid & 31) == 0) red[tid >> 5] = s;
    __syncthreads();
    float mean = (red[0] + red[1] + red[2] + red[3]) * (1.f / Cn);
    __syncthreads();

    float d0 = v0 - mean, d1 = v1 - mean, d2 = v2 - mean;
    float sq = d0 * d0 + d1 * d1 + d2 * d2;
    for (int o = 16; o > 0; o >>= 1) sq += __shfl_xor_sync(0xffffffffu, sq, o);
    if ((tid & 31) == 0) red[tid >> 5] = sq;
    __syncthreads();
    float var = (red[0] + red[1] + red[2] + red[3]) * (1.f / Cn);
    float inv = rsqrtf(var + EPSn);

    out[base + tid]       = g[tid]       * d0 * inv + bb[tid];
    out[base + tid + 128] = g[tid + 128] * d1 * inv + bb[tid + 128];
    out[base + tid + 256] = g[tid + 256] * d2 * inv + bb[tid + 256];
}

// ---------------- host orchestration ----------------
extern "C" void kernel_launch(void* const* d_in, const int* in_sizes, int n_in,
                              void* d_out, int out_size)
{
    (void)in_sizes; (void)n_in; (void)out_size;
    const float* x    = (const float*)d_in[0];
    const float* q1w  = (const float*)d_in[1];
    const float* q1b  = (const float*)d_in[2];
    const float* k1w  = (const float*)d_in[3];
    const float* k1b  = (const float*)d_in[4];
    const float* v1w  = (const float*)d_in[5];
    const float* v1b  = (const float*)d_in[6];
    const float* p1w  = (const float*)d_in[7];
    const float* p1b  = (const float*)d_in[8];
    const float* ln1g = (const float*)d_in[9];
    const float* ln1b = (const float*)d_in[10];
    const float* q2w  = (const float*)d_in[11];
    const float* q2b  = (const float*)d_in[12];
    const float* k2w  = (const float*)d_in[13];
    const float* k2b  = (const float*)d_in[14];
    const float* v2w  = (const float*)d_in[15];
    const float* v2b  = (const float*)d_in[16];
    const float* p2w  = (const float*)d_in[17];
    const float* p2b  = (const float*)d_in[18];
    const float* ln2g = (const float*)d_in[19];
    const float* ln2b = (const float*)d_in[20];
    const float* f1w  = (const float*)d_in[21];
    const float* f1b  = (const float*)d_in[22];
    const float* f2w  = (const float*)d_in[23];
    const float* f2b  = (const float*)d_in[24];
    const float* ln3g = (const float*)d_in[25];
    const float* ln3b = (const float*)d_in[26];
    float* out = (float*)d_out;

    float *pwq, *pwk, *pwv, *pq, *pk, *pv, *po, *pp, *pr1, *pr2, *ph;
    cudaGetSymbolAddress((void**)&pwq, g_wq);
    cudaGetSymbolAddress((void**)&pwk, g_wk);
    cudaGetSymbolAddress((void**)&pwv, g_wv);
    cudaGetSymbolAddress((void**)&pq,  g_q);
    cudaGetSymbolAddress((void**)&pk,  g_k);
    cudaGetSymbolAddress((void**)&pv,  g_v);
    cudaGetSymbolAddress((void**)&po,  g_o);
    cudaGetSymbolAddress((void**)&pp,  g_p);
    cudaGetSymbolAddress((void**)&pr1, g_r1);
    cudaGetSymbolAddress((void**)&pr2, g_r2);
    cudaGetSymbolAddress((void**)&ph,  g_h);

    const int nW = Hn * Cn * HDn;
    const int nPairs = Bn * Hn * Tn * 32;
    const dim3 gC(Cn / 128, BTn / 128);

    auto run_layer = [&](const float* xin,
                         const float* qw, const float* qb,
                         const float* kw, const float* kb,
                         const float* vw, const float* vb,
                         const float* pw, const float* pb,
                         const float* lng, const float* lnb,
                         float* rout) {
        repack_w<<<(nW + 255) / 256, 256>>>(qw, pwq, nW);
        repack_w<<<(nW + 255) / 256, 256>>>(kw, pwk, nW);
        repack_w<<<(nW + 255) / 256, 256>>>(vw, pwv, nW);
        sgemm128<<<gC, 256>>>(xin, pwq, qb, pq, BTn, Cn, Cn, 2);
        sgemm128<<<gC, 256>>>(xin, pwk, kb, pk, BTn, Cn, Cn, 2);
        sgemm128<<<gC, 256>>>(xin, pwv, vb, pv, BTn, Cn, Cn, 2);
        rope_k<<<(nPairs + 255) / 256, 256>>>(pq, nPairs);
        rope_k<<<(nPairs + 255) / 256, 256>>>(pk, nPairs);
        attn_k<<<dim3(Tn / 8, Bn * Hn), 256>>>(pq, pk, pv, po);
        sgemm128<<<gC, 256>>>(po, pw, pb, pp, BTn, Cn, Cn, 0);
        ln_res_k<<<BTn, 128>>>(xin, pp, lng, lnb, rout);
    };

    run_layer(x,   q1w, q1b, k1w, k1b, v1w, v1b, p1w, p1b, ln1g, ln1b, pr1);
    run_layer(pr1, q2w, q2b, k2w, k2b, v2w, v2b, p2w, p2b, ln2g, ln2b, pr2);

    sgemm128<<<dim3(FFn / 128, BTn / 128), 256>>>(pr2, f1w, f1b, ph, BTn, FFn, Cn, 1);
    sgemm128<<<dim3(Cn / 128, BTn / 128), 256>>>(ph, f2w, f2b, pp, BTn, Cn, FFn, 0);
    ln_res_k<<<BTn, 128>>>(pr2, pp, ln3g, ln3b, out);
}

// round 2
// speedup vs baseline: 1.4799x; 1.4799x over previous
#include <cuda_runtime.h>
#include <math.h>

#define Bn 64
#define Tn 512
#define Cn 384
#define Hn 6
#define HDn 64
#define FFn 1536
#define BTn (Bn*Tn)
#define EPSn 1e-5f
#define SMS 136   // smem row stride (floats): conflict-free frag loads

// ---------------- scratch (device globals; no runtime allocation) ----------------
__device__ float g_wqkv[Cn*3*Cn];
__device__ float g_bqkv[3*Cn];
__device__ float g_q[(size_t)Bn*Hn*Tn*HDn];
__device__ float g_k[(size_t)Bn*Hn*Tn*HDn];
__device__ float g_v[(size_t)Bn*Hn*Tn*HDn];
__device__ float g_o[(size_t)BTn*Cn];
__device__ float g_p[(size_t)BTn*Cn];
__device__ float g_r1[(size_t)BTn*Cn];
__device__ float g_r2[(size_t)BTn*Cn];
__device__ float g_h[(size_t)BTn*FFn];

// ---------------- pack QKV weights [H,C,HD]x3 -> [C, 3C] row-major -------------
__global__ void qkv_pack_w(const float* __restrict__ qw, const float* __restrict__ kw,
                           const float* __restrict__ vw, float* __restrict__ o) {
    int idx = blockIdx.x * blockDim.x + threadIdx.x;
    if (idx >= Cn * 3 * Cn) return;
    int c = idx / (3 * Cn);
    int col = idx % (3 * Cn);
    int mat = col / Cn;
    int local = col % Cn;
    int h = local >> 6, d = local & 63;
    const float* w = (mat == 0) ? qw : (mat == 1) ? kw : vw;
    o[idx] = w[((size_t)h * Cn + c) * HDn + d];
}
__global__ void qkv_pack_b(const float* __restrict__ qb, const float* __restrict__ kb,
                           const float* __restrict__ vb, float* __restrict__ o) {
    int i = threadIdx.x + blockIdx.x * blockDim.x;
    if (i >= 3 * Cn) return;
    const float* b = (i < Cn) ? qb : (i < 2 * Cn) ? kb : vb;
    o[i] = b[i % Cn];
}

// ---------------- tf32 mma helpers ----------------
__device__ __forceinline__ unsigned f2tf(float x) {
    unsigned r; asm("cvt.rna.tf32.f32 %0, %1;" : "=r"(r) : "f"(x)); return r;
}
__device__ __forceinline__ void mma8(float* d, const unsigned* a, const unsigned* b) {
    asm("mma.sync.aligned.m16n8k8.row.col.f32.tf32.tf32.f32 "
        "{%0,%1,%2,%3},{%4,%5,%6,%7},{%8,%9},{%0,%1,%2,%3};"
        : "+f"(d[0]), "+f"(d[1]), "+f"(d[2]), "+f"(d[3])
        : "r"(a[0]), "r"(a[1]), "r"(a[2]), "r"(a[3]), "r"(b[0]), "r"(b[1]));
}

// ---------------- tf32 tensor-core GEMM: C[M,N] = A[M,K] @ B[K,N] + bias --------
// block tile 128x128, warp tile 64x32 (warps 2x4), K step 16, smem double buffer
// flags: bit0 relu; bit1 qkv-scatter (+rope on q/k), writes to oq/ok/ov
__global__ __launch_bounds__(256) void gemm_tf32(
    const float* __restrict__ A, const float* __restrict__ Bm,
    const float* __restrict__ bias, float* __restrict__ Cout,
    int M, int N, int K, int flags,
    float* __restrict__ oq, float* __restrict__ ok, float* __restrict__ ov)
{
    __shared__ float As[2][16 * SMS];
    __shared__ float Bs[2][16 * SMS];

    const int tid = threadIdx.x;
    const int lane = tid & 31, warp = tid >> 5;
    const int warpM = warp >> 2, warpN = warp & 3;   // 2 x 4
    const int bm = blockIdx.y * 128, bn = blockIdx.x * 128;
    const int qq = lane & 3, gg = lane >> 2;

    // global load mapping
    const int aRow = tid >> 1;                 // 0..127
    const int aK = (tid & 1) * 8;              // 0 or 8
    const int bK = tid >> 4;                   // 0..15
    const int bN4 = (tid & 15) * 4;            // 0..60
    const float* Ap = A + (size_t)(bm + aRow) * K + aK;
    const float* Bp = Bm + (size_t)bK * N + bn + bN4;

    float acc[4][4][4];
#pragma unroll
    for (int i = 0; i < 4; i++)
#pragma unroll
        for (int j = 0; j < 4; j++)
#pragma unroll
            for (int r = 0; r < 4; r++) acc[i][j][r] = 0.f;

    float4 sa0, sa1, sb0, sb1;
    // preload kt = 0
    sa0 = *(const float4*)(Ap);
    sa1 = *(const float4*)(Ap + 4);
    sb0 = *(const float4*)(Bp);
    sb1 = *(const float4*)(Bp + 64);
    {
        float* as = As[0]; float* bs = Bs[0];
        as[(aK + 0) * SMS + aRow] = sa0.x; as[(aK + 1) * SMS + aRow] = sa0.y;
        as[(aK + 2) * SMS + aRow] = sa0.z; as[(aK + 3) * SMS + aRow] = sa0.w;
        as[(aK + 4) * SMS + aRow] = sa1.x; as[(aK + 5) * SMS + aRow] = sa1.y;
        as[(aK + 6) * SMS + aRow] = sa1.z; as[(aK + 7) * SMS + aRow] = sa1.w;
        *(float4*)(&bs[bK * SMS + bN4]) = sb0;
        *(float4*)(&bs[bK * SMS + bN4 + 64]) = sb1;
    }
    __syncthreads();

    const int KT = K >> 4;
    for (int kt = 0; kt < KT; kt++) {
        if (kt + 1 < KT) {
            const float* ap = Ap + (size_t)(kt + 1) * 16;
            const float* bp = Bp + (size_t)(kt + 1) * 16 * N;
            sa0 = *(const float4*)(ap);
            sa1 = *(const float4*)(ap + 4);
            sb0 = *(const float4*)(bp);
            sb1 = *(const float4*)(bp + 64);
        }
        const float* as = As[kt & 1];
        const float* bs = Bs[kt & 1];
#pragma unroll
        for (int kk = 0; kk < 16; kk += 8) {
            unsigned af[4][4], bf[4][2];
#pragma unroll
            for (int mi = 0; mi < 4; mi++) {
                int m0 = warpM * 64 + mi * 16 + gg;
                af[mi][0] = f2tf(as[(kk + qq) * SMS + m0]);
                af[mi][1] = f2tf(as[(kk + qq) * SMS + m0 + 8]);
                af[mi][2] = f2tf(as[(kk + qq + 4) * SMS + m0]);
                af[mi][3] = f2tf(as[(kk + qq + 4) * SMS + m0 + 8]);
            }
#pragma unroll
            for (int ni = 0; ni < 4; ni++) {
                int n0 = warpN * 32 + ni * 8 + gg;
                bf[ni][0] = f2tf(bs[(kk + qq) * SMS + n0]);
                bf[ni][1] = f2tf(bs[(kk + qq + 4) * SMS + n0]);
            }
#pragma unroll
            for (int mi = 0; mi < 4; mi++)
#pragma unroll
                for (int ni = 0; ni < 4; ni++)
                    mma8(acc[mi][ni], af[mi], bf[ni]);
        }
        if (kt + 1 < KT) {
            float* asw = As[(kt + 1) & 1]; float* bsw = Bs[(kt + 1) & 1];
            asw[(aK + 0) * SMS + aRow] = sa0.x; asw[(aK + 1) * SMS + aRow] = sa0.y;
            asw[(aK + 2) * SMS + aRow] = sa0.z; asw[(aK + 3) * SMS + aRow] = sa0.w;
            asw[(aK + 4) * SMS + aRow] = sa1.x; asw[(aK + 5) * SMS + aRow] = sa1.y;
            asw[(aK + 6) * SMS + aRow] = sa1.z; asw[(aK + 7) * SMS + aRow] = sa1.w;
            *(float4*)(&bsw[bK * SMS + bN4]) = sb0;
            *(float4*)(&bsw[bK * SMS + bN4 + 64]) = sb1;
            __syncthreads();
        }
    }

    // -------- epilogue --------
    const bool relu = (flags & 1) != 0;
    const bool qkv = (flags & 2) != 0;

#pragma unroll
    for (int mi = 0; mi < 4; mi++) {
        int row0 = bm + warpM * 64 + mi * 16 + gg;
        float sn[2], cs[2];
        if (qkv) {
            sincosf((float)(row0 & 511), &sn[0], &cs[0]);
            sincosf((float)((row0 + 8) & 511), &sn[1], &cs[1]);
        }
#pragma unroll
        for (int ni = 0; ni < 4; ni++) {
            int col = bn + warpN * 32 + ni * 8 + (lane & 3) * 2;
            float b0 = bias[col], b1 = bias[col + 1];
#pragma unroll
            for (int half = 0; half < 2; half++) {
                int row = row0 + half * 8;
                float xr = acc[mi][ni][half * 2 + 0] + b0;
                float xi = acc[mi][ni][half * 2 + 1] + b1;
                if (qkv) {
                    int mat = col / Cn;        // 0=q 1=k 2=v (uniform per block)
                    if (mat < 2) {
                        float nr = cs[half] * xr - sn[half] * xi;
                        float ni2 = sn[half] * xr + cs[half] * xi;
                        xr = nr; xi = ni2;
                    }
                    int local = col - mat * Cn;
                    int h = local >> 6, d = local & 63;
                    int bb = row >> 9, t = row & 511;
                    float* dst = (mat == 0) ? oq : (mat == 1) ? ok : ov;
                    float2* p = (float2*)(dst + (((size_t)(bb * Hn + h) * Tn + t) * HDn + d));
                    *p = make_float2(xr, xi);
                } else {
                    if (relu) { xr = fmaxf(xr, 0.f); xi = fmaxf(xi, 0.f); }
                    float2* p = (float2*)(Cout + (size_t)row * N + col);
                    *p = make_float2(xr, xi);
                }
            }
        }
    }
}

// ---------------- causal flash attention: 8 warps/block = 8 queries ----------------
__global__ __launch_bounds__(256) void attn_k(
    const float* __restrict__ q, const float* __restrict__ k,
    const float* __restrict__ v, float* __restrict__ o)
{
    const int bh = blockIdx.y;
    const int warp = threadIdx.x >> 5, lane = threadIdx.x & 31;
    const int t = blockIdx.x * 8 + warp;
    const size_t base = (size_t)bh * Tn * HDn;
    __shared__ float Ks[32][64];
    __shared__ float Vs[32][64];

    const float q_a = q[base + (size_t)t * 64 + lane];
    const float q_b = q[base + (size_t)t * 64 + 32 + lane];

    float m = -INFINITY, l = 0.f, acc_a = 0.f, acc_b = 0.f;
    const int tmax = blockIdx.x * 8 + 7;
    const float scale = 0.051031036307982884f;

    for (int s0 = 0; s0 <= tmax; s0 += 32) {
        __syncthreads();
        for (int i = threadIdx.x; i < 32 * 64; i += 256) {
            int ss = i >> 6, d = i & 63;
            Ks[ss][d] = k[base + (size_t)(s0 + ss) * 64 + d];
            Vs[ss][d] = v[base + (size_t)(s0 + ss) * 64 + d];
        }
        __syncthreads();
        int jmax = min(32, tmax - s0 + 1);
        for (int j = 0; j < jmax; ++j) {
            float p = q_a * Ks[j][lane] + q_b * Ks[j][lane + 32];
            p += __shfl_xor_sync(0xffffffffu, p, 16);
            p += __shfl_xor_sync(0xffffffffu, p, 8);
            p += __shfl_xor_sync(0xffffffffu, p, 4);
            p += __shfl_xor_sync(0xffffffffu, p, 2);
            p += __shfl_xor_sync(0xffffffffu, p, 1);
            int s = s0 + j;
            if (s <= t) {
                float sc = p * scale;
                float mn = fmaxf(m, sc);
                float corr = __expf(m - mn);
                float pe = __expf(sc - mn);
                l = l * corr + pe;
                acc_a = acc_a * corr + pe * Vs[j][lane];
                acc_b = acc_b * corr + pe * Vs[j][lane + 32];
                m = mn;
            }
        }
    }
    const int b = bh / Hn, h = bh % Hn;
    const float inv = 1.f / l;
    size_t ob = ((size_t)(b * Tn + t)) * Cn + h * HDn;
    o[ob + lane]      = acc_a * inv;
    o[ob + 32 + lane] = acc_b * inv;
}

// ---------------- fused residual-add + LayerNorm (row = 384) ----------------
__global__ __launch_bounds__(128) void ln_res_k(
    const float* __restrict__ x, const float* __restrict__ y,
    const float* __restrict__ g, const float* __restrict__ bb,
    float* __restrict__ out)
{
    __shared__ float red[4];
    const int row = blockIdx.x;
    const int tid = threadIdx.x;
    const size_t base = (size_t)row * Cn;
    float v0 = x[base + tid]       + y[base + tid];
    float v1 = x[base + tid + 128] + y[base + tid + 128];
    float v2 = x[base + tid + 256] + y[base + tid + 256];

    float s = v0 + v1 + v2;
    for (int o = 16; o > 0; o >>= 1) s += __shfl_xor_sync(0xffffffffu, s, o);
    if ((tid & 31) == 0) red[tid >> 5] = s;
    __syncthreads();
    float mean = (red[0] + red[1] + red[2] + red[3]) * (1.f / Cn);
    __syncthreads();

    float d0 = v0 - mean, d1 = v1 - mean, d2 = v2 - mean;
    float sq = d0 * d0 + d1 * d1 + d2 * d2;
    for (int o = 16; o > 0; o >>= 1) sq += __shfl_xor_sync(0xffffffffu, sq, o);
    if ((tid & 31) == 0) red[tid >> 5] = sq;
    __syncthreads();
    float var = (red[0] + red[1] + red[2] + red[3]) * (1.f / Cn);
    float inv = rsqrtf(var + EPSn);

    out[base + tid]       = g[tid]       * d0 * inv + bb[tid];
    out[base + tid + 128] = g[tid + 128] * d1 * inv + bb[tid + 128];
    out[base + tid + 256] = g[tid + 256] * d2 * inv + bb[tid + 256];
}

// ---------------- host orchestration ----------------
extern "C" void kernel_launch(void* const* d_in, const int* in_sizes, int n_in,
                              void* d_out, int out_size)
{
    (void)in_sizes; (void)n_in; (void)out_size;
    const float* x    = (const float*)d_in[0];
    const float* q1w  = (const float*)d_in[1];
    const float* q1b  = (const float*)d_in[2];
    const float* k1w  = (const float*)d_in[3];
    const float* k1b  = (const float*)d_in[4];
    const float* v1w  = (const float*)d_in[5];
    const float* v1b  = (const float*)d_in[6];
    const float* p1w  = (const float*)d_in[7];
    const float* p1b  = (const float*)d_in[8];
    const float* ln1g = (const float*)d_in[9];
    const float* ln1b = (const float*)d_in[10];
    const float* q2w  = (const float*)d_in[11];
    const float* q2b  = (const float*)d_in[12];
    const float* k2w  = (const float*)d_in[13];
    const float* k2b  = (const float*)d_in[14];
    const float* v2w  = (const float*)d_in[15];
    const float* v2b  = (const float*)d_in[16];
    const float* p2w  = (const float*)d_in[17];
    const float* p2b  = (const float*)d_in[18];
    const float* ln2g = (const float*)d_in[19];
    const float* ln2b = (const float*)d_in[20];
    const float* f1w  = (const float*)d_in[21];
    const float* f1b  = (const float*)d_in[22];
    const float* f2w  = (const float*)d_in[23];
    const float* f2b  = (const float*)d_in[24];
    const float* ln3g = (const float*)d_in[25];
    const float* ln3b = (const float*)d_in[26];
    float* out = (float*)d_out;

    float *pwqkv, *pbqkv, *pq, *pk, *pv, *po, *pp, *pr1, *pr2, *ph;
    cudaGetSymbolAddress((void**)&pwqkv, g_wqkv);
    cudaGetSymbolAddress((void**)&pbqkv, g_bqkv);
    cudaGetSymbolAddress((void**)&pq,  g_q);
    cudaGetSymbolAddress((void**)&pk,  g_k);
    cudaGetSymbolAddress((void**)&pv,  g_v);
    cudaGetSymbolAddress((void**)&po,  g_o);
    cudaGetSymbolAddress((void**)&pp,  g_p);
    cudaGetSymbolAddress((void**)&pr1, g_r1);
    cudaGetSymbolAddress((void**)&pr2, g_r2);
    cudaGetSymbolAddress((void**)&ph,  g_h);

    const int nPack = Cn * 3 * Cn;

    auto run_layer = [&](const float* xin,
                         const float* qw, const float* qb,
                         const float* kw, const float* kb,
                         const float* vw, const float* vb,
                         const float* pw, const float* pb,
                         const float* lng, const float* lnb,
                         float* rout) {
        qkv_pack_w<<<(nPack + 255) / 256, 256>>>(qw, kw, vw, pwqkv);
        qkv_pack_b<<<(3 * Cn + 255) / 256, 256>>>(qb, kb, vb, pbqkv);
        gemm_tf32<<<dim3(3 * Cn / 128, BTn / 128), 256>>>(
            xin, pwqkv, pbqkv, nullptr, BTn, 3 * Cn, Cn, 2, pq, pk, pv);
        attn_k<<<dim3(Tn / 8, Bn * Hn), 256>>>(pq, pk, pv, po);
        gemm_tf32<<<dim3(Cn / 128, BTn / 128), 256>>>(
            po, pw, pb, pp, BTn, Cn, Cn, 0, nullptr, nullptr, nullptr);
        ln_res_k<<<BTn, 128>>>(xin, pp, lng, lnb, rout);
    };

    run_layer(x,   q1w, q1b, k1w, k1b, v1w, v1b, p1w, p1b, ln1g, ln1b, pr1);
    run_layer(pr1, q2w, q2b, k2w, k2b, v2w, v2b, p2w, p2b, ln2g, ln2b, pr2);

    gemm_tf32<<<dim3(FFn / 128, BTn / 128), 256>>>(
        pr2, f1w, f1b, ph, BTn, FFn, Cn, 1, nullptr, nullptr, nullptr);
    gemm_tf32<<<dim3(Cn / 128, BTn / 128), 256>>>(
        ph, f2w, f2b, pp, BTn, Cn, FFn, 0, nullptr, nullptr, nullptr);
    ln_res_k<<<BTn, 128>>>(pr2, pp, ln3g, ln3b, out);
}

// round 3
// speedup vs baseline: 4.7856x; 3.2338x over previous
#include <cuda_runtime.h>
#include <math.h>

#define Bn 64
#define Tn 512
#define Cn 384
#define Hn 6
#define HDn 64
#define FFn 1536
#define BTn (Bn*Tn)
#define EPSn 1e-5f
#define SMS 136   // gemm smem row stride

// attention smem strides (floats)
#define STQ 68
#define STK 68
#define STV 36
#define STP 36

// ---------------- scratch (device globals; no runtime allocation) ----------------
__device__ float g_wqkv[Cn*3*Cn];
__device__ float g_bqkv[3*Cn];
__device__ float g_q[(size_t)Bn*Hn*Tn*HDn];
__device__ float g_k[(size_t)Bn*Hn*Tn*HDn];
__device__ float g_v[(size_t)Bn*Hn*Tn*HDn];
__device__ float g_o[(size_t)BTn*Cn];
__device__ float g_p[(size_t)BTn*Cn];
__device__ float g_r1[(size_t)BTn*Cn];
__device__ float g_r2[(size_t)BTn*Cn];
__device__ float g_h[(size_t)BTn*FFn];

// ---------------- pack QKV weights [H,C,HD]x3 -> [C, 3C] row-major -------------
__global__ void qkv_pack_w(const float* __restrict__ qw, const float* __restrict__ kw,
                           const float* __restrict__ vw, float* __restrict__ o) {
    int idx = blockIdx.x * blockDim.x + threadIdx.x;
    if (idx >= Cn * 3 * Cn) return;
    int c = idx / (3 * Cn);
    int col = idx % (3 * Cn);
    int mat = col / Cn;
    int local = col % Cn;
    int h = local >> 6, d = local & 63;
    const float* w = (mat == 0) ? qw : (mat == 1) ? kw : vw;
    o[idx] = w[((size_t)h * Cn + c) * HDn + d];
}
__global__ void qkv_pack_b(const float* __restrict__ qb, const float* __restrict__ kb,
                           const float* __restrict__ vb, float* __restrict__ o) {
    int i = threadIdx.x + blockIdx.x * blockDim.x;
    if (i >= 3 * Cn) return;
    const float* b = (i < Cn) ? qb : (i < 2 * Cn) ? kb : vb;
    o[i] = b[i % Cn];
}

// ---------------- tf32 mma helpers ----------------
__device__ __forceinline__ unsigned f2tf(float x) {
    unsigned r; asm("cvt.rna.tf32.f32 %0, %1;" : "=r"(r) : "f"(x)); return r;
}
__device__ __forceinline__ void mma8(float* d, const unsigned* a, const unsigned* b) {
    asm("mma.sync.aligned.m16n8k8.row.col.f32.tf32.tf32.f32 "
        "{%0,%1,%2,%3},{%4,%5,%6,%7},{%8,%9},{%0,%1,%2,%3};"
        : "+f"(d[0]), "+f"(d[1]), "+f"(d[2]), "+f"(d[3])
        : "r"(a[0]), "r"(a[1]), "r"(a[2]), "r"(a[3]), "r"(b[0]), "r"(b[1]));
}

// ---------------- tf32 tensor-core GEMM (unchanged from R2) --------
__global__ __launch_bounds__(256) void gemm_tf32(
    const float* __restrict__ A, const float* __restrict__ Bm,
    const float* __restrict__ bias, float* __restrict__ Cout,
    int M, int N, int K, int flags,
    float* __restrict__ oq, float* __restrict__ ok, float* __restrict__ ov)
{
    __shared__ float As[2][16 * SMS];
    __shared__ float Bs[2][16 * SMS];

    const int tid = threadIdx.x;
    const int lane = tid & 31, warp = tid >> 5;
    const int warpM = warp >> 2, warpN = warp & 3;
    const int bm = blockIdx.y * 128, bn = blockIdx.x * 128;
    const int qq = lane & 3, gg = lane >> 2;

    const int aRow = tid >> 1;
    const int aK = (tid & 1) * 8;
    const int bK = tid >> 4;
    const int bN4 = (tid & 15) * 4;
    const float* Ap = A + (size_t)(bm + aRow) * K + aK;
    const float* Bp = Bm + (size_t)bK * N + bn + bN4;

    float acc[4][4][4];
#pragma unroll
    for (int i = 0; i < 4; i++)
#pragma unroll
        for (int j = 0; j < 4; j++)
#pragma unroll
            for (int r = 0; r < 4; r++) acc[i][j][r] = 0.f;

    float4 sa0, sa1, sb0, sb1;
    sa0 = *(const float4*)(Ap);
    sa1 = *(const float4*)(Ap + 4);
    sb0 = *(const float4*)(Bp);
    sb1 = *(const float4*)(Bp + 64);
    {
        float* as = As[0]; float* bs = Bs[0];
        as[(aK + 0) * SMS + aRow] = sa0.x; as[(aK + 1) * SMS + aRow] = sa0.y;
        as[(aK + 2) * SMS + aRow] = sa0.z; as[(aK + 3) * SMS + aRow] = sa0.w;
        as[(aK + 4) * SMS + aRow] = sa1.x; as[(aK + 5) * SMS + aRow] = sa1.y;
        as[(aK + 6) * SMS + aRow] = sa1.z; as[(aK + 7) * SMS + aRow] = sa1.w;
        *(float4*)(&bs[bK * SMS + bN4]) = sb0;
        *(float4*)(&bs[bK * SMS + bN4 + 64]) = sb1;
    }
    __syncthreads();

    const int KT = K >> 4;
    for (int kt = 0; kt < KT; kt++) {
        if (kt + 1 < KT) {
            const float* ap = Ap + (size_t)(kt + 1) * 16;
            const float* bp = Bp + (size_t)(kt + 1) * 16 * N;
            sa0 = *(const float4*)(ap);
            sa1 = *(const float4*)(ap + 4);
            sb0 = *(const float4*)(bp);
            sb1 = *(const float4*)(bp + 64);
        }
        const float* as = As[kt & 1];
        const float* bs = Bs[kt & 1];
#pragma unroll
        for (int kk = 0; kk < 16; kk += 8) {
            unsigned af[4][4], bf[4][2];
#pragma unroll
            for (int mi = 0; mi < 4; mi++) {
                int m0 = warpM * 64 + mi * 16 + gg;
                af[mi][0] = f2tf(as[(kk + qq) * SMS + m0]);
                af[mi][1] = f2tf(as[(kk + qq) * SMS + m0 + 8]);
                af[mi][2] = f2tf(as[(kk + qq + 4) * SMS + m0]);
                af[mi][3] = f2tf(as[(kk + qq + 4) * SMS + m0 + 8]);
            }
#pragma unroll
            for (int ni = 0; ni < 4; ni++) {
                int n0 = warpN * 32 + ni * 8 + gg;
                bf[ni][0] = f2tf(bs[(kk + qq) * SMS + n0]);
                bf[ni][1] = f2tf(bs[(kk + qq + 4) * SMS + n0]);
            }
#pragma unroll
            for (int mi = 0; mi < 4; mi++)
#pragma unroll
                for (int ni = 0; ni < 4; ni++)
                    mma8(acc[mi][ni], af[mi], bf[ni]);
        }
        if (kt + 1 < KT) {
            float* asw = As[(kt + 1) & 1]; float* bsw = Bs[(kt + 1) & 1];
            asw[(aK + 0) * SMS + aRow] = sa0.x; asw[(aK + 1) * SMS + aRow] = sa0.y;
            asw[(aK + 2) * SMS + aRow] = sa0.z; asw[(aK + 3) * SMS + aRow] = sa0.w;
            asw[(aK + 4) * SMS + aRow] = sa1.x; asw[(aK + 5) * SMS + aRow] = sa1.y;
            asw[(aK + 6) * SMS + aRow] = sa1.z; asw[(aK + 7) * SMS + aRow] = sa1.w;
            *(float4*)(&bsw[bK * SMS + bN4]) = sb0;
            *(float4*)(&bsw[bK * SMS + bN4 + 64]) = sb1;
            __syncthreads();
        }
    }

    const bool relu = (flags & 1) != 0;
    const bool qkv = (flags & 2) != 0;

#pragma unroll
    for (int mi = 0; mi < 4; mi++) {
        int row0 = bm + warpM * 64 + mi * 16 + gg;
        float sn[2], cs[2];
        if (qkv) {
            sincosf((float)(row0 & 511), &sn[0], &cs[0]);
            sincosf((float)((row0 + 8) & 511), &sn[1], &cs[1]);
        }
#pragma unroll
        for (int ni = 0; ni < 4; ni++) {
            int col = bn + warpN * 32 + ni * 8 + (lane & 3) * 2;
            float b0 = bias[col], b1 = bias[col + 1];
#pragma unroll
            for (int half = 0; half < 2; half++) {
                int row = row0 + half * 8;
                float xr = acc[mi][ni][half * 2 + 0] + b0;
                float xi = acc[mi][ni][half * 2 + 1] + b1;
                if (qkv) {
                    int mat = col / Cn;
                    if (mat < 2) {
                        float nr = cs[half] * xr - sn[half] * xi;
                        float ni2 = sn[half] * xr + cs[half] * xi;
                        xr = nr; xi = ni2;
                    }
                    int local = col - mat * Cn;
                    int h = local >> 6, d = local & 63;
                    int bb = row >> 9, t = row & 511;
                    float* dst = (mat == 0) ? oq : (mat == 1) ? ok : ov;
                    float2* p = (float2*)(dst + (((size_t)(bb * Hn + h) * Tn + t) * HDn + d));
                    *p = make_float2(xr, xi);
                } else {
                    if (relu) { xr = fmaxf(xr, 0.f); xi = fmaxf(xi, 0.f); }
                    float2* p = (float2*)(Cout + (size_t)row * N + col);
                    *p = make_float2(xr, xi);
                }
            }
        }
    }
}

// ---------------- tensor-core causal flash attention ----------------
// block = 128 threads (4 warps), 64-query tile, 32-key tiles, tf32 mma
__global__ __launch_bounds__(128) void attn_mma(
    const float* __restrict__ q, const float* __restrict__ k,
    const float* __restrict__ v, float* __restrict__ o)
{
    __shared__ float sm[32 * STK + 64 * STV];   // Ks | Vt ; Q staging (64*STQ=4352) overlays
    __shared__ float Ps[64 * STP];
    float* Ks = sm;
    float* Vt = sm + 32 * STK;

    const int bh = blockIdx.y;
    const int qt = blockIdx.x;
    const int tid = threadIdx.x;
    const int warp = tid >> 5, lane = tid & 31;
    const int gg = lane >> 2, qq = lane & 3;
    const size_t base = (size_t)bh * Tn * HDn;
    const int q0 = qt * 64;
    const float scale = 0.051031036307982884f;   // 1/sqrt(384)

    // stage Q (scaled) into sm, stride STQ
    for (int i = tid; i < 64 * 16; i += 128) {
        int r = i >> 4, d4 = (i & 15) * 4;
        float4 t4 = *(const float4*)(q + base + (size_t)(q0 + r) * 64 + d4);
        float* dst = sm + r * STQ + d4;
        dst[0] = t4.x * scale; dst[1] = t4.y * scale;
        dst[2] = t4.z * scale; dst[3] = t4.w * scale;
    }
    __syncthreads();

    // build Q A-fragments (tf32), 8 k-steps over d=64
    unsigned qf[8][4];
    {
        const float* qr = sm + (warp * 16 + gg) * STQ;
#pragma unroll
        for (int ks = 0; ks < 8; ks++) {
            qf[ks][0] = f2tf(qr[ks * 8 + qq]);
            qf[ks][1] = f2tf(qr[8 * STQ + ks * 8 + qq]);
            qf[ks][2] = f2tf(qr[ks * 8 + qq + 4]);
            qf[ks][3] = f2tf(qr[8 * STQ + ks * 8 + qq + 4]);
        }
    }
    __syncthreads();   // Q staging done; Ks/Vt region reusable

    float oacc[8][4];
#pragma unroll
    for (int i = 0; i < 8; i++)
#pragma unroll
        for (int r = 0; r < 4; r++) oacc[i][r] = 0.f;
    float m0 = -INFINITY, m1 = -INFINITY, l0 = 0.f, l1 = 0.f;

    const int row0g = q0 + warp * 16 + gg;
    const int row1g = row0g + 8;
    const int ktiles = 2 * qt + 2;

    for (int kt = 0; kt < ktiles; kt++) {
        const int kbase = kt * 32;
        // load K tile [32][64] and V tile transposed [64][32]
        for (int i = tid; i < 32 * 16; i += 128) {
            int r = i >> 4, d4 = (i & 15) * 4;
            float4 t4 = *(const float4*)(k + base + (size_t)(kbase + r) * 64 + d4);
            *(float4*)(Ks + r * STK + d4) = t4;
            float4 u4 = *(const float4*)(v + base + (size_t)(kbase + r) * 64 + d4);
            Vt[(d4 + 0) * STV + r] = u4.x;
            Vt[(d4 + 1) * STV + r] = u4.y;
            Vt[(d4 + 2) * STV + r] = u4.z;
            Vt[(d4 + 3) * STV + r] = u4.w;
        }
        __syncthreads();

        // S = Q K^T  (16 rows x 32 keys per warp)
        float s[4][4];
#pragma unroll
        for (int nt = 0; nt < 4; nt++)
#pragma unroll
            for (int r = 0; r < 4; r++) s[nt][r] = 0.f;
#pragma unroll
        for (int ks = 0; ks < 8; ks++) {
            unsigned bf[4][2];
#pragma unroll
            for (int nt = 0; nt < 4; nt++) {
                bf[nt][0] = f2tf(Ks[(nt * 8 + gg) * STK + ks * 8 + qq]);
                bf[nt][1] = f2tf(Ks[(nt * 8 + gg) * STK + ks * 8 + qq + 4]);
            }
#pragma unroll
            for (int nt = 0; nt < 4; nt++) mma8(s[nt], qf[ks], bf[nt]);
        }

        // causal mask (only diagonal 64-key block needs it)
        if (kt >= 2 * qt) {
#pragma unroll
            for (int nt = 0; nt < 4; nt++) {
                int c0 = kbase + nt * 8 + 2 * qq;
                if (c0 > row0g)     s[nt][0] = -1e30f;
                if (c0 + 1 > row0g) s[nt][1] = -1e30f;
                if (c0 > row1g)     s[nt][2] = -1e30f;
                if (c0 + 1 > row1g) s[nt][3] = -1e30f;
            }
        }

        // online softmax
        float rm0 = -1e30f, rm1 = -1e30f;
#pragma unroll
        for (int nt = 0; nt < 4; nt++) {
            rm0 = fmaxf(rm0, fmaxf(s[nt][0], s[nt][1]));
            rm1 = fmaxf(rm1, fmaxf(s[nt][2], s[nt][3]));
        }
        rm0 = fmaxf(rm0, __shfl_xor_sync(0xffffffffu, rm0, 1));
        rm0 = fmaxf(rm0, __shfl_xor_sync(0xffffffffu, rm0, 2));
        rm1 = fmaxf(rm1, __shfl_xor_sync(0xffffffffu, rm1, 1));
        rm1 = fmaxf(rm1, __shfl_xor_sync(0xffffffffu, rm1, 2));
        float nm0 = fmaxf(m0, rm0), nm1 = fmaxf(m1, rm1);
        float corr0 = __expf(m0 - nm0), corr1 = __expf(m1 - nm1);
        float rs0 = 0.f, rs1 = 0.f;
#pragma unroll
        for (int nt = 0; nt < 4; nt++) {
            s[nt][0] = __expf(s[nt][0] - nm0);
            s[nt][1] = __expf(s[nt][1] - nm0);
            s[nt][2] = __expf(s[nt][2] - nm1);
            s[nt][3] = __expf(s[nt][3] - nm1);
            rs0 += s[nt][0] + s[nt][1];
            rs1 += s[nt][2] + s[nt][3];
        }
        rs0 += __shfl_xor_sync(0xffffffffu, rs0, 1);
        rs0 += __shfl_xor_sync(0xffffffffu, rs0, 2);
        rs1 += __shfl_xor_sync(0xffffffffu, rs1, 1);
        rs1 += __shfl_xor_sync(0xffffffffu, rs1, 2);
        l0 = l0 * corr0 + rs0;
        l1 = l1 * corr1 + rs1;
        m0 = nm0; m1 = nm1;
#pragma unroll
        for (int nt = 0; nt < 8; nt++) {
            oacc[nt][0] *= corr0; oacc[nt][1] *= corr0;
            oacc[nt][2] *= corr1; oacc[nt][3] *= corr1;
        }

        // stage P (warp-private rows) for A-fragment reload
        {
            float* pr = Ps + (warp * 16 + gg) * STP;
#pragma unroll
            for (int nt = 0; nt < 4; nt++) {
                *(float2*)(pr + nt * 8 + 2 * qq) = make_float2(s[nt][0], s[nt][1]);
                *(float2*)(pr + 8 * STP + nt * 8 + 2 * qq) = make_float2(s[nt][2], s[nt][3]);
            }
        }
        __syncwarp();

        // O += P V   (k-dim = 32 keys, 4 k-steps; n = 64 d, 8 n-tiles)
#pragma unroll
        for (int ks = 0; ks < 4; ks++) {
            unsigned af[4];
            const float* pr = Ps + (warp * 16 + gg) * STP + ks * 8;
            af[0] = f2tf(pr[qq]);
            af[1] = f2tf(pr[8 * STP + qq]);
            af[2] = f2tf(pr[qq + 4]);
            af[3] = f2tf(pr[8 * STP + qq + 4]);
#pragma unroll
            for (int nt = 0; nt < 8; nt++) {
                unsigned bf2[2];
                bf2[0] = f2tf(Vt[(nt * 8 + gg) * STV + ks * 8 + qq]);
                bf2[1] = f2tf(Vt[(nt * 8 + gg) * STV + ks * 8 + qq + 4]);
                mma8(oacc[nt], af, bf2);
            }
        }
        __syncthreads();   // protect Ks/Vt before next tile's load
    }

    // epilogue: normalize and scatter to [BT, C]
    const float inv0 = 1.f / l0, inv1 = 1.f / l1;
    const int b = bh / Hn, h = bh % Hn;
    float* p0 = o + ((size_t)(b * Tn + row0g)) * Cn + h * 64;
    float* p1 = o + ((size_t)(b * Tn + row1g)) * Cn + h * 64;
#pragma unroll
    for (int nt = 0; nt < 8; nt++) {
        *(float2*)(p0 + nt * 8 + 2 * qq) = make_float2(oacc[nt][0] * inv0, oacc[nt][1] * inv0);
        *(float2*)(p1 + nt * 8 + 2 * qq) = make_float2(oacc[nt][2] * inv1, oacc[nt][3] * inv1);
    }
}

// ---------------- fused residual-add + LayerNorm (row = 384) ----------------
__global__ __launch_bounds__(128) void ln_res_k(
    const float* __restrict__ x, const float* __restrict__ y,
    const float* __restrict__ g, const float* __restrict__ bb,
    float* __restrict__ out)
{
    __shared__ float red[4];
    const int row = blockIdx.x;
    const int tid = threadIdx.x;
    const size_t base = (size_t)row * Cn;
    float v0 = x[base + tid]       + y[base + tid];
    float v1 = x[base + tid + 128] + y[base + tid + 128];
    float v2 = x[base + tid + 256] + y[base + tid + 256];

    float s = v0 + v1 + v2;
    for (int o = 16; o > 0; o >>= 1) s += __shfl_xor_sync(0xffffffffu, s, o);
    if ((tid & 31) == 0) red[tid >> 5] = s;
    __syncthreads();
    float mean = (red[0] + red[1] + red[2] + red[3]) * (1.f / Cn);
    __syncthreads();

    float d0 = v0 - mean, d1 = v1 - mean, d2 = v2 - mean;
    float sq = d0 * d0 + d1 * d1 + d2 * d2;
    for (int o = 16; o > 0; o >>= 1) sq += __shfl_xor_sync(0xffffffffu, sq, o);
    if ((tid & 31) == 0) red[tid >> 5] = sq;
    __syncthreads();
    float var = (red[0] + red[1] + red[2] + red[3]) * (1.f / Cn);
    float inv = rsqrtf(var + EPSn);

    out[base + tid]       = g[tid]       * d0 * inv + bb[tid];
    out[base + tid + 128] = g[tid + 128] * d1 * inv + bb[tid + 128];
    out[base + tid + 256] = g[tid + 256] * d2 * inv + bb[tid + 256];
}

// ---------------- host orchestration ----------------
extern "C" void kernel_launch(void* const* d_in, const int* in_sizes, int n_in,
                              void* d_out, int out_size)
{
    (void)in_sizes; (void)n_in; (void)out_size;
    const float* x    = (const float*)d_in[0];
    const float* q1w  = (const float*)d_in[1];
    const float* q1b  = (const float*)d_in[2];
    const float* k1w  = (const float*)d_in[3];
    const float* k1b  = (const float*)d_in[4];
    const float* v1w  = (const float*)d_in[5];
    const float* v1b  = (const float*)d_in[6];
    const float* p1w  = (const float*)d_in[7];
    const float* p1b  = (const float*)d_in[8];
    const float* ln1g = (const float*)d_in[9];
    const float* ln1b = (const float*)d_in[10];
    const float* q2w  = (const float*)d_in[11];
    const float* q2b  = (const float*)d_in[12];
    const float* k2w  = (const float*)d_in[13];
    const float* k2b  = (const float*)d_in[14];
    const float* v2w  = (const float*)d_in[15];
    const float* v2b  = (const float*)d_in[16];
    const float* p2w  = (const float*)d_in[17];
    const float* p2b  = (const float*)d_in[18];
    const float* ln2g = (const float*)d_in[19];
    const float* ln2b = (const float*)d_in[20];
    const float* f1w  = (const float*)d_in[21];
    const float* f1b  = (const float*)d_in[22];
    const float* f2w  = (const float*)d_in[23];
    const float* f2b  = (const float*)d_in[24];
    const float* ln3g = (const float*)d_in[25];
    const float* ln3b = (const float*)d_in[26];
    float* out = (float*)d_out;

    float *pwqkv, *pbqkv, *pq, *pk, *pv, *po, *pp, *pr1, *pr2, *ph;
    cudaGetSymbolAddress((void**)&pwqkv, g_wqkv);
    cudaGetSymbolAddress((void**)&pbqkv, g_bqkv);
    cudaGetSymbolAddress((void**)&pq,  g_q);
    cudaGetSymbolAddress((void**)&pk,  g_k);
    cudaGetSymbolAddress((void**)&pv,  g_v);
    cudaGetSymbolAddress((void**)&po,  g_o);
    cudaGetSymbolAddress((void**)&pp,  g_p);
    cudaGetSymbolAddress((void**)&pr1, g_r1);
    cudaGetSymbolAddress((void**)&pr2, g_r2);
    cudaGetSymbolAddress((void**)&ph,  g_h);

    const int nPack = Cn * 3 * Cn;

    auto run_layer = [&](const float* xin,
                         const float* qw, const float* qb,
                         const float* kw, const float* kb,
                         const float* vw, const float* vb,
                         const float* pw, const float* pb,
                         const float* lng, const float* lnb,
                         float* rout) {
        qkv_pack_w<<<(nPack + 255) / 256, 256>>>(qw, kw, vw, pwqkv);
        qkv_pack_b<<<(3 * Cn + 255) / 256, 256>>>(qb, kb, vb, pbqkv);
        gemm_tf32<<<dim3(3 * Cn / 128, BTn / 128), 256>>>(
            xin, pwqkv, pbqkv, nullptr, BTn, 3 * Cn, Cn, 2, pq, pk, pv);
        attn_mma<<<dim3(Tn / 64, Bn * Hn), 128>>>(pq, pk, pv, po);
        gemm_tf32<<<dim3(Cn / 128, BTn / 128), 256>>>(
            po, pw, pb, pp, BTn, Cn, Cn, 0, nullptr, nullptr, nullptr);
        ln_res_k<<<BTn, 128>>>(xin, pp, lng, lnb, rout);
    };

    run_layer(x,   q1w, q1b, k1w, k1b, v1w, v1b, p1w, p1b, ln1g, ln1b, pr1);
    run_layer(pr1, q2w, q2b, k2w, k2b, v2w, v2b, p2w, p2b, ln2g, ln2b, pr2);

    gemm_tf32<<<dim3(FFn / 128, BTn / 128), 256>>>(
        pr2, f1w, f1b, ph, BTn, FFn, Cn, 1, nullptr, nullptr, nullptr);
    gemm_tf32<<<dim3(Cn / 128, BTn / 128), 256>>>(
        ph, f2w, f2b, pp, BTn, Cn, FFn, 0, nullptr, nullptr, nullptr);
    ln_res_k<<<BTn, 128>>>(pr2, pp, ln3g, ln3b, out);
}